// round 5
// baseline (speedup 1.0000x reference)
#include <cuda_runtime.h>
#include <math.h>

#define BB 8
#define NHEADS 16
#define DH 48
#define DD 768
#define P2 256

typedef unsigned long long ull;

// ---- f32x2 packed helpers (Blackwell FFMA2) ----
__device__ __forceinline__ ull pk2(float lo, float hi) {
    ull r; asm("mov.b64 %0,{%1,%2};" : "=l"(r) : "f"(lo), "f"(hi)); return r;
}
__device__ __forceinline__ ull dup2(float v) {
    ull r; asm("mov.b64 %0,{%1,%1};" : "=l"(r) : "f"(v)); return r;
}
__device__ __forceinline__ void fma2(ull& d, ull a, ull b) {
    asm("fma.rn.f32x2 %0,%1,%2,%0;" : "+l"(d) : "l"(a), "l"(b));
}
__device__ __forceinline__ float2 up2(ull v) {
    float2 r; asm("mov.b64 {%0,%1},%2;" : "=f"(r.x), "=f"(r.y) : "l"(v)); return r;
}

__device__ __forceinline__ float4 shfl_xor4(float4 v, int m) {
    const unsigned FULL = 0xffffffffu;
    v.x = __shfl_xor_sync(FULL, v.x, m);
    v.y = __shfl_xor_sync(FULL, v.y, m);
    v.z = __shfl_xor_sync(FULL, v.z, m);
    v.w = __shfl_xor_sync(FULL, v.w, m);
    return v;
}
__device__ __forceinline__ float4 f4add(float4 a, float4 b) {
    return make_float4(a.x+b.x, a.y+b.y, a.z+b.z, a.w+b.w);
}

// Scratch: windowified Q/K/V  [b][head][n][pix4][dh]  (25MB each)
__device__ float g_Q[BB*NHEADS*P2*4*DH];
__device__ float g_K[BB*NHEADS*P2*4*DH];
__device__ float g_V[BB*NHEADS*P2*4*DH];

// ---------------------------------------------------------------------------
// Fused BN-fold + depthwise 5x5 conv for q,k,v (q pre-scaled by d^-0.5).
// Block: 256 thr = 32 channels x 8 slots. Grid: (24 chunks * 4 rowquads, 8 b).
// Folded weights pre-duplicated (f32x2) in SMEM; inner loop = LDS.64 + FFMA2.
// Output windowified: pixel (r,cl) -> n=(r%16)*16+(cl%16), pix=(r/16)*2+(cl/16)
// ---------------------------------------------------------------------------
__global__ __launch_bounds__(256) void conv_kernel(const float* __restrict__ x,
                                                   const float* __restrict__ conv_w,
                                                   const float* __restrict__ gamma,
                                                   const float* __restrict__ beta,
                                                   const float* __restrict__ mean,
                                                   const float* __restrict__ var) {
    __shared__ ull  wdup[3][25][32];   // folded weights, duplicated to both halves
    __shared__ ull  bdup[3][32];
    __shared__ float sinv[3][32];

    int tid   = threadIdx.x;
    int b     = blockIdx.y;
    int chunk = blockIdx.x >> 2;
    int rquad = blockIdx.x & 3;
    int lane5 = tid & 31;
    int slot  = tid >> 5;             // 0..7
    int c0    = chunk * 32;
    int c     = c0 + lane5;

    // ---- prologue: fold BN, duplicate, stage to smem ----
    if (tid < 96) {
        int j  = tid / 32;
        int cl = tid % 32;
        int t  = j * DD + c0 + cl;
        float inv = gamma[t] * rsqrtf(var[t] + 1e-5f);
        float bs  = beta[t] - mean[t] * inv;
        if (j == 0) { inv *= 0.03608439182435161f; bs *= 0.03608439182435161f; } // 768^-0.5
        sinv[j][cl] = inv;
        bdup[j][cl] = dup2(bs);
    }
    __syncthreads();
    for (int f = tid; f < 3 * 800; f += 256) {
        int j   = f / 800;
        int rem = f - j * 800;
        int ch  = rem / 25;
        int tap = rem - ch * 25;
        float wv = conv_w[(size_t)(j * DD + c0 + ch) * 25 + tap] * sinv[j][ch];
        wdup[j][tap][ch] = dup2(wv);
    }
    __syncthreads();

    ull biasr[3];
#pragma unroll
    for (int j = 0; j < 3; j++) biasr[j] = bdup[j][lane5];

    const float* xb = x + (size_t)b * 1024 * DD + c;

#pragma unroll 1
    for (int gi = 0; gi < 4; gi++) {
        int g    = slot * 4 + gi;       // 0..31
        int row  = rquad * 8 + (g >> 2);
        int col0 = (g & 3) * 8;

        ull acc[3][4];
#pragma unroll
        for (int j = 0; j < 3; j++)
#pragma unroll
            for (int p = 0; p < 4; p++) acc[j][p] = biasr[j];

#pragma unroll
        for (int dy = 0; dy < 5; dy++) {
            int r = row + dy - 2;
            if ((unsigned)r < 32u) {
                const float* xr = xb + (size_t)(r * 32) * DD;
                float xv[12];
#pragma unroll
                for (int i = 0; i < 12; i++) {
                    int cl = col0 + i - 2;
                    xv[i] = ((unsigned)cl < 32u) ? xr[cl * DD] : 0.f;
                }
                ull xp[11];
#pragma unroll
                for (int i = 0; i < 11; i++) xp[i] = pk2(xv[i], xv[i + 1]);
#pragma unroll
                for (int j = 0; j < 3; j++) {
#pragma unroll
                    for (int dx = 0; dx < 5; dx++) {
                        ull wd = wdup[j][dy * 5 + dx][lane5];   // LDS.64 broadcast
                        fma2(acc[j][0], wd, xp[dx + 0]);
                        fma2(acc[j][1], wd, xp[dx + 2]);
                        fma2(acc[j][2], wd, xp[dx + 4]);
                        fma2(acc[j][3], wd, xp[dx + 6]);
                    }
                }
            }
        }

        int head  = c / DH;
        int cc    = c % DH;
        int pix   = ((row >> 4) << 1) + (col0 >> 4);
        int nbase = (row & 15) * 16 + (col0 & 15);
        int obase = (((b * NHEADS + head) * P2 + nbase) * 4 + pix) * DH + cc;
#pragma unroll
        for (int p = 0; p < 4; p++) {
            float2 aq = up2(acc[0][p]);
            float2 ak = up2(acc[1][p]);
            float2 av = up2(acc[2][p]);
            int off0 = obase + (2 * p) * (4 * DH);
            int off1 = off0 + 4 * DH;
            g_Q[off0] = aq.x;  g_Q[off1] = aq.y;
            g_K[off0] = ak.x;  g_K[off1] = ak.y;
            g_V[off0] = av.x;  g_V[off1] = av.y;
        }
    }
}

// ---------------------------------------------------------------------------
// Fused top-8 + sparse window attention. One warp per (b, head, window n).
// K/V gathered coalesced (4-lane groups, contiguous runs), kept in REGISTERS.
// Logits and A@V computed as per-lane partials over the gather layout, then
// shuffle reduce-scattered. No K/V smem staging at all.
// ---------------------------------------------------------------------------
__global__ __launch_bounds__(128) void attn_kernel(const float* __restrict__ adj,
                                                   float* __restrict__ out) {
    __shared__ __align__(16) float s_at[4][128];   // per-warp softmax weights [kk][qp]
    const unsigned FULL = 0xffffffffu;
    int warp = threadIdx.x >> 5;
    int lane = threadIdx.x & 31;
    int widx = blockIdx.x * 4 + warp;      // 0..32767
    int bh   = widx >> 8;
    int n    = widx & 255;
    int b    = bh >> 4;
    int head = bh & 15;
    int la3  = lane & 3;
    int run  = lane >> 2;

    // ---- top-8 of gen_adj row (256 values, 8 per lane) ----
    const float* rowp = adj + ((size_t)bh * 256 + n) * 256;
    float vals[8];
#pragma unroll
    for (int j = 0; j < 8; j++) vals[j] = rowp[j * 32 + lane];

    int mysel = 0;
    for (int it = 0; it < 8; it++) {
        float bv = -1e30f;
        int bi = 0;
#pragma unroll
        for (int j = 0; j < 8; j++)
            if (vals[j] > bv) { bv = vals[j]; bi = j * 32 + lane; }
#pragma unroll
        for (int off = 16; off > 0; off >>= 1) {
            float ov = __shfl_down_sync(FULL, bv, off);
            int   oi = __shfl_down_sync(FULL, bi, off);
            if (ov > bv) { bv = ov; bi = oi; }
        }
        bi = __shfl_sync(FULL, bi, 0);
        if (lane == it) mysel = bi;
#pragma unroll
        for (int j = 0; j < 8; j++)
            if (bi == j * 32 + lane) vals[j] = -1e30f;
    }

    // ---- coalesced K gather into registers ----
    // lane holds, for run = lane>>2: K4[3p+m] = k(pix p, ch4 la3+4m)
    int sel = __shfl_sync(FULL, mysel, run);
    const float4* kg = (const float4*)(g_K + ((size_t)(bh * 256 + sel) * 4) * DH);
    const float4* vg = (const float4*)(g_V + ((size_t)(bh * 256 + sel) * 4) * DH);
    float4 K4[12];
#pragma unroll
    for (int i = 0; i < 12; i++) K4[i] = kg[4 * i + la3];

    // ---- partial logits over this lane's 12 channels (q read uniform LDG) ----
    const float4* qb = (const float4*)(g_Q + (size_t)widx * 192);
    float pl[4][4];   // [qp][pix]
#pragma unroll
    for (int qp = 0; qp < 4; qp++)
#pragma unroll
        for (int p = 0; p < 4; p++) pl[qp][p] = 0.f;

#pragma unroll
    for (int m = 0; m < 3; m++) {
        float4 qv[4];
#pragma unroll
        for (int qp = 0; qp < 4; qp++) qv[qp] = __ldg(&qb[qp * 12 + 4 * m + la3]);
#pragma unroll
        for (int p = 0; p < 4; p++) {
            float4 kv = K4[3 * p + m];
#pragma unroll
            for (int qp = 0; qp < 4; qp++)
                pl[qp][p] += qv[qp].x * kv.x + qv[qp].y * kv.y
                           + qv[qp].z * kv.z + qv[qp].w * kv.w;
        }
    }

    // ---- prefetch V (covers latency under the reductions/softmax below) ----
    float4 V4[12];
#pragma unroll
    for (int i = 0; i < 12; i++) V4[i] = vg[4 * i + la3];

    // ---- reduce-scatter logits within 4-lane group: pix la3 -> lane ----
    int pb0 = la3 & 1, pb1 = (la3 >> 1) & 1;
    float l[4];
#pragma unroll
    for (int qp = 0; qp < 4; qp++) {
        float give, keep, t0, t1;
        give = pb0 ? pl[qp][0] : pl[qp][1];
        keep = pb0 ? pl[qp][1] : pl[qp][0];
        t0 = keep + __shfl_xor_sync(FULL, give, 1);     // pix 0/1 -> pix pb0
        give = pb0 ? pl[qp][2] : pl[qp][3];
        keep = pb0 ? pl[qp][3] : pl[qp][2];
        t1 = keep + __shfl_xor_sync(FULL, give, 1);     // pix 2/3 -> pix 2+pb0
        give = pb1 ? t0 : t1;
        keep = pb1 ? t1 : t0;
        l[qp] = keep + __shfl_xor_sync(FULL, give, 2);  // -> pix la3 == lane&3
    }

    // ---- softmax across 32 lanes per qp-row (lane == kk) ----
    float a[4];
#pragma unroll
    for (int qp = 0; qp < 4; qp++) {
        float m = l[qp];
#pragma unroll
        for (int off = 16; off > 0; off >>= 1)
            m = fmaxf(m, __shfl_xor_sync(FULL, m, off));
        float e = __expf(l[qp] - m);
        float s = e;
#pragma unroll
        for (int off = 16; off > 0; off >>= 1)
            s += __shfl_xor_sync(FULL, s, off);
        a[qp] = __fdividef(e, s);
    }
    ((float4*)s_at[warp])[lane] = make_float4(a[0], a[1], a[2], a[3]);
    __syncwarp();

    // ---- A@V partials: lane's 12 channels over its run's 4 keys ----
    float4 opart[4][3];   // [qp][m]
#pragma unroll
    for (int qp = 0; qp < 4; qp++)
#pragma unroll
        for (int m = 0; m < 3; m++) opart[qp][m] = make_float4(0.f, 0.f, 0.f, 0.f);

#pragma unroll
    for (int p = 0; p < 4; p++) {
        float4 ap = ((const float4*)s_at[warp])[run * 4 + p];   // a[0..3][kk=run*4+p]
#pragma unroll
        for (int m = 0; m < 3; m++) {
            float4 vv = V4[3 * p + m];
            opart[0][m].x += ap.x * vv.x; opart[0][m].y += ap.x * vv.y;
            opart[0][m].z += ap.x * vv.z; opart[0][m].w += ap.x * vv.w;
            opart[1][m].x += ap.y * vv.x; opart[1][m].y += ap.y * vv.y;
            opart[1][m].z += ap.y * vv.z; opart[1][m].w += ap.y * vv.w;
            opart[2][m].x += ap.z * vv.x; opart[2][m].y += ap.z * vv.y;
            opart[2][m].z += ap.z * vv.z; opart[2][m].w += ap.z * vv.w;
            opart[3][m].x += ap.w * vv.x; opart[3][m].y += ap.w * vv.y;
            opart[3][m].z += ap.w * vv.z; opart[3][m].w += ap.w * vv.w;
        }
    }

    // ---- reduce-scatter across the 8 groups (sum over runs) ----
    int gb0 = (lane >> 2) & 1, gb1 = (lane >> 3) & 1, gb2 = (lane >> 4) & 1;

    float4 t1[2][3];                      // r1 (xor 4): keep qp with qp&1 == gb0
#pragma unroll
    for (int q2 = 0; q2 < 2; q2++)
#pragma unroll
        for (int m = 0; m < 3; m++) {
            float4 give = gb0 ? opart[2 * q2][m] : opart[2 * q2 + 1][m];
            float4 keep = gb0 ? opart[2 * q2 + 1][m] : opart[2 * q2][m];
            t1[q2][m] = f4add(keep, shfl_xor4(give, 4));
        }

    float4 t2[3];                         // r2 (xor 8): keep q2 == gb1
#pragma unroll
    for (int m = 0; m < 3; m++) {
        float4 give = gb1 ? t1[0][m] : t1[1][m];
        float4 keep = gb1 ? t1[1][m] : t1[0][m];
        t2[m] = f4add(keep, shfl_xor4(give, 8));
    }

    float r[3][2];                        // r3 (xor 16): keep comps f with f&1 == gb2
#pragma unroll
    for (int m = 0; m < 3; m++) {
        float give0 = gb2 ? t2[m].x : t2[m].y;
        float give1 = gb2 ? t2[m].z : t2[m].w;
        float keep0 = gb2 ? t2[m].y : t2[m].x;
        float keep1 = gb2 ? t2[m].w : t2[m].z;
        r[m][0] = keep0 + __shfl_xor_sync(FULL, give0, 16);
        r[m][1] = keep1 + __shfl_xor_sync(FULL, give1, 16);
    }

    // ---- store: lane holds out[qp = (lane>>2)&3][ch = 4*la3 + 16*m + 2*fi + gb2] ----
    int wy = n >> 4, wx = n & 15;
    int qp = (lane >> 2) & 3;
    int row = ((qp & 1) << 4) + wy;
    int col = ((qp >> 1) << 4) + wx;
    float* op = out + ((size_t)b * 1024 + row * 32 + col) * 768 + head * 48;
#pragma unroll
    for (int m = 0; m < 3; m++)
#pragma unroll
        for (int fi = 0; fi < 2; fi++)
            op[4 * la3 + 16 * m + 2 * fi + gb2] = r[m][fi];
}

// ---------------------------------------------------------------------------
extern "C" void kernel_launch(void* const* d_in, const int* in_sizes, int n_in,
                              void* d_out, int out_size) {
    const float* x      = (const float*)d_in[0];
    // d_in[1] = noise (unused by reference)
    const float* adj    = (const float*)d_in[2];
    const float* conv_w = (const float*)d_in[3];
    const float* gamma  = (const float*)d_in[4];
    const float* beta   = (const float*)d_in[5];
    const float* mean   = (const float*)d_in[6];
    const float* var    = (const float*)d_in[7];
    // d_in[8] = sparsity (constant 8, compiled in)
    float* out = (float*)d_out;

    conv_kernel<<<dim3(96, 8), 256>>>(x, conv_w, gamma, beta, mean, var);
    attn_kernel<<<8192, 128>>>(adj, out);
}

// round 6
// speedup vs baseline: 1.3954x; 1.3954x over previous
#include <cuda_runtime.h>
#include <math.h>

#define BB 8
#define NHEADS 16
#define DH 48
#define DD 768
#define P2 256

typedef unsigned long long ull;

// ---- f32x2 packed helpers (Blackwell FFMA2) ----
__device__ __forceinline__ ull pk2(float lo, float hi) {
    ull r; asm("mov.b64 %0,{%1,%2};" : "=l"(r) : "f"(lo), "f"(hi)); return r;
}
__device__ __forceinline__ ull dup2(float v) {
    ull r; asm("mov.b64 %0,{%1,%1};" : "=l"(r) : "f"(v)); return r;
}
__device__ __forceinline__ void fma2(ull& d, ull a, ull b) {
    asm("fma.rn.f32x2 %0,%1,%2,%0;" : "+l"(d) : "l"(a), "l"(b));
}
__device__ __forceinline__ float2 up2(ull v) {
    float2 r; asm("mov.b64 {%0,%1},%2;" : "=f"(r.x), "=f"(r.y) : "l"(v)); return r;
}

// Scratch: windowified Q/K/V  [b][head][n][pix4][dh]  (25MB each), 128B aligned
__device__ __align__(128) float g_Q[BB*NHEADS*P2*4*DH];
__device__ __align__(128) float g_K[BB*NHEADS*P2*4*DH];
__device__ __align__(128) float g_V[BB*NHEADS*P2*4*DH];

// ---------------------------------------------------------------------------
// Fused BN-fold + depthwise 5x5 conv for q,k,v (q pre-scaled by d^-0.5).
// Block: 128 thr = 32 channels x 4 slots. Grid: (24 chunks * 4 rowquads, 8 b).
// (exact R4 version — best measured conv)
// ---------------------------------------------------------------------------
__global__ __launch_bounds__(128) void conv_kernel(const float* __restrict__ x,
                                                   const float* __restrict__ conv_w,
                                                   const float* __restrict__ gamma,
                                                   const float* __restrict__ beta,
                                                   const float* __restrict__ mean,
                                                   const float* __restrict__ var) {
    __shared__ ull  wdup[3][25][32];
    __shared__ ull  bdup[3][32];
    __shared__ float sinv[3][32];

    int tid   = threadIdx.x;
    int b     = blockIdx.y;
    int chunk = blockIdx.x >> 2;
    int rquad = blockIdx.x & 3;
    int lane5 = tid & 31;
    int slot  = tid >> 5;             // 0..3
    int c0    = chunk * 32;
    int c     = c0 + lane5;

    if (tid < 96) {
        int j  = tid / 32;
        int cl = tid % 32;
        int t  = j * DD + c0 + cl;
        float inv = gamma[t] * rsqrtf(var[t] + 1e-5f);
        float bs  = beta[t] - mean[t] * inv;
        if (j == 0) { inv *= 0.03608439182435161f; bs *= 0.03608439182435161f; } // 768^-0.5
        sinv[j][cl] = inv;
        bdup[j][cl] = dup2(bs);
    }
    __syncthreads();
    for (int f = tid; f < 3 * 800; f += 128) {
        int j   = f / 800;
        int rem = f - j * 800;
        int ch  = rem / 25;
        int tap = rem - ch * 25;
        float wv = conv_w[(size_t)(j * DD + c0 + ch) * 25 + tap] * sinv[j][ch];
        wdup[j][tap][ch] = dup2(wv);
    }
    __syncthreads();

    ull biasr[3];
#pragma unroll
    for (int j = 0; j < 3; j++) biasr[j] = bdup[j][lane5];

    const float* xb = x + (size_t)b * 1024 * DD + c;

#pragma unroll 1
    for (int gi = 0; gi < 8; gi++) {
        int g    = slot * 8 + gi;       // 0..31
        int row  = rquad * 8 + (g >> 2);
        int col0 = (g & 3) * 8;

        ull acc[3][4];
#pragma unroll
        for (int j = 0; j < 3; j++)
#pragma unroll
            for (int p = 0; p < 4; p++) acc[j][p] = biasr[j];

#pragma unroll
        for (int dy = 0; dy < 5; dy++) {
            int r = row + dy - 2;
            if ((unsigned)r < 32u) {
                const float* xr = xb + (size_t)(r * 32) * DD;
                float xv[12];
#pragma unroll
                for (int i = 0; i < 12; i++) {
                    int cl = col0 + i - 2;
                    xv[i] = ((unsigned)cl < 32u) ? xr[cl * DD] : 0.f;
                }
                ull xp[11];
#pragma unroll
                for (int i = 0; i < 11; i++) xp[i] = pk2(xv[i], xv[i + 1]);
#pragma unroll
                for (int j = 0; j < 3; j++) {
#pragma unroll
                    for (int dx = 0; dx < 5; dx++) {
                        ull wd = wdup[j][dy * 5 + dx][lane5];   // LDS.64 broadcast
                        fma2(acc[j][0], wd, xp[dx + 0]);
                        fma2(acc[j][1], wd, xp[dx + 2]);
                        fma2(acc[j][2], wd, xp[dx + 4]);
                        fma2(acc[j][3], wd, xp[dx + 6]);
                    }
                }
            }
        }

        int head  = c / DH;
        int cc    = c % DH;
        int pix   = ((row >> 4) << 1) + (col0 >> 4);
        int nbase = (row & 15) * 16 + (col0 & 15);
        int obase = (((b * NHEADS + head) * P2 + nbase) * 4 + pix) * DH + cc;
#pragma unroll
        for (int p = 0; p < 4; p++) {
            float2 aq = up2(acc[0][p]);
            float2 ak = up2(acc[1][p]);
            float2 av = up2(acc[2][p]);
            int off0 = obase + (2 * p) * (4 * DH);
            int off1 = off0 + 4 * DH;
            g_Q[off0] = aq.x;  g_Q[off1] = aq.y;
            g_K[off0] = ak.x;  g_K[off1] = ak.y;
            g_V[off0] = av.x;  g_V[off1] = av.y;
        }
    }
}

// ---------------------------------------------------------------------------
// Fused top-8 + sparse window attention. One warp per (b, head, window n).
// Flat-map coalesced gather: LDG.128 inst j covers contiguous 512B of the
// concatenated 8x768B run space (4 lines/inst). K staged in smem (stride-52
// pad, conflict-free), reloaded to per-lane columns; buffer reused for V.
// Top-8 via exact 32-bit monotone-uint REDUX.
// ---------------------------------------------------------------------------
struct WarpSmem {
    float buf[32 * 52];   // K stage, then V  (float4-aligned rows)
    float qs[4 * 48];     // q (pre-scaled by conv)
    float at[128];        // softmax weights [kk][qp]
};

__global__ __launch_bounds__(128) void attn_kernel(const float* __restrict__ adj,
                                                   float* __restrict__ out) {
    __shared__ __align__(16) WarpSmem sm[4];
    const unsigned FULL = 0xffffffffu;
    int warp = threadIdx.x >> 5;
    int lane = threadIdx.x & 31;
    int widx = blockIdx.x * 4 + warp;      // 0..32767
    int bh   = widx >> 8;
    int n    = widx & 255;
    int b    = bh >> 4;
    int head = bh & 15;
    WarpSmem& S = sm[warp];

    // ---- stage q into smem early ----
    {
        const float4* qsrc = (const float4*)(g_Q + (size_t)widx * 192);
        ((float4*)S.qs)[lane] = qsrc[lane];
        if (lane < 16) ((float4*)S.qs)[32 + lane] = qsrc[32 + lane];
    }

    // ---- top-8 of gen_adj row: exact monotone-uint REDUX argmax ----
    const float* rowp = adj + ((size_t)bh * 256 + n) * 256;
    unsigned m8[8];
#pragma unroll
    for (int j = 0; j < 8; j++) {
        unsigned u = __float_as_uint(rowp[j * 32 + lane]);
        m8[j] = (u & 0x80000000u) ? ~u : (u | 0x80000000u);
    }

    int mysel = 0;
#pragma unroll 1
    for (int it = 0; it < 8; it++) {
        unsigned bv = m8[0];
        int bj = 0;
#pragma unroll
        for (int j = 1; j < 8; j++)
            if (m8[j] > bv) { bv = m8[j]; bj = j; }
        unsigned wmax = __reduce_max_sync(FULL, bv);
        unsigned bal  = __ballot_sync(FULL, bv == wmax);
        int wl  = __ffs(bal) - 1;
        int bjw = __shfl_sync(FULL, bj, wl);
        if (lane == it) mysel = bjw * 32 + wl;
        if (lane == wl) m8[bj] = 0u;
    }

    // ---- flat-map gather precompute: inst j covers f4 indices j*32+lane ----
    // run space: 8 runs x 48 f4 each (contiguous per run in g_K/g_V).
    int pack[12];
#pragma unroll
    for (int j = 0; j < 12; j++) {
        int f   = j * 32 + lane;
        int run = f / 48;
        int idx = f - run * 48;
        int pix = idx / 12;
        int c4  = idx - pix * 12;
        int sel = __shfl_sync(FULL, mysel, run);
        int goff = sel * 48 + idx;                 // f4 offset within bh region
        int slt  = (run * 4 + pix) * 13 + c4;      // smem f4 slot
        pack[j] = (goff << 9) | slt;
    }

    const float4* kg = (const float4*)g_K + (size_t)bh * 12288;
    const float4* vg = (const float4*)g_V + (size_t)bh * 12288;
    float4* buf4 = (float4*)S.buf;

    // ---- K gather -> smem (each inst: 512B contiguous, 4 lines) ----
#pragma unroll
    for (int j = 0; j < 12; j++)
        buf4[pack[j] & 511] = kg[pack[j] >> 9];
    __syncwarp();

    // ---- reload own key column (conflict-free: bank = 5*lane mod 8) ----
    float k[48];
#pragma unroll
    for (int i = 0; i < 12; i++) {
        float4 t = buf4[lane * 13 + i];
        k[4*i] = t.x; k[4*i+1] = t.y; k[4*i+2] = t.z; k[4*i+3] = t.w;
    }
    __syncwarp();

    // ---- V gather into the SAME buffer ----
#pragma unroll
    for (int j = 0; j < 12; j++)
        buf4[pack[j] & 511] = vg[pack[j] >> 9];

    // ---- logits[qp] for this lane's key column (dot over 48) ----
    float l[4] = {0.f, 0.f, 0.f, 0.f};
#pragma unroll
    for (int ch = 0; ch < 12; ch++) {
#pragma unroll
        for (int qp = 0; qp < 4; qp++) {
            float4 qv = ((const float4*)&S.qs[qp * 48])[ch];   // broadcast LDS.128
            l[qp] += qv.x * k[4*ch] + qv.y * k[4*ch+1]
                   + qv.z * k[4*ch+2] + qv.w * k[4*ch+3];
        }
    }

    // ---- softmax across 32 lanes per qp-row ----
    float a[4];
#pragma unroll
    for (int qp = 0; qp < 4; qp++) {
        float m = l[qp];
#pragma unroll
        for (int off = 16; off > 0; off >>= 1)
            m = fmaxf(m, __shfl_xor_sync(FULL, m, off));
        float e = __expf(l[qp] - m);
        float s = e;
#pragma unroll
        for (int off = 16; off > 0; off >>= 1)
            s += __shfl_xor_sync(FULL, s, off);
        a[qp] = __fdividef(e, s);
    }
    ((float4*)S.at)[lane] = make_float4(a[0], a[1], a[2], a[3]);
    __syncwarp();

    // ---- out[qp][c] = sum_kk a[qp][kk] * v[kk][c] ----
    float o1[4] = {0,0,0,0}, o2[4] = {0,0,0,0};
#pragma unroll
    for (int kk = 0; kk < 32; kk++) {
        float4 av = ((const float4*)S.at)[kk];          // broadcast
        float v1 = S.buf[kk * 52 + lane];
        float v2 = S.buf[kk * 52 + 32 + lane];          // garbage for lane>=16, never stored
        o1[0] += av.x * v1; o1[1] += av.y * v1; o1[2] += av.z * v1; o1[3] += av.w * v1;
        o2[0] += av.x * v2; o2[1] += av.y * v2; o2[2] += av.z * v2; o2[3] += av.w * v2;
    }

    // ---- scatter to output ----
    int wy = n >> 4, wx = n & 15;
    float* ob = out + (size_t)b * 1024 * 768 + head * 48;
#pragma unroll
    for (int p = 0; p < 4; p++) {
        int row = ((p & 1) << 4) + wy;
        int col = ((p >> 1) << 4) + wx;
        int off = (row * 32 + col) * 768;
        ob[off + lane] = o1[p];
        if (lane < 16) ob[off + 32 + lane] = o2[p];
    }
}

// ---------------------------------------------------------------------------
extern "C" void kernel_launch(void* const* d_in, const int* in_sizes, int n_in,
                              void* d_out, int out_size) {
    const float* x      = (const float*)d_in[0];
    // d_in[1] = noise (unused by reference)
    const float* adj    = (const float*)d_in[2];
    const float* conv_w = (const float*)d_in[3];
    const float* gamma  = (const float*)d_in[4];
    const float* beta   = (const float*)d_in[5];
    const float* mean   = (const float*)d_in[6];
    const float* var    = (const float*)d_in[7];
    // d_in[8] = sparsity (constant 8, compiled in)
    float* out = (float*)d_out;

    conv_kernel<<<dim3(96, 8), 128>>>(x, conv_w, gamma, beta, mean, var);
    attn_kernel<<<8192, 128>>>(adj, out);
}

// round 7
// speedup vs baseline: 1.5445x; 1.1069x over previous
#include <cuda_runtime.h>
#include <math.h>

#define BB 8
#define NHEADS 16
#define DH 48
#define DD 768
#define P2 256

typedef unsigned long long ull;

// ---- f32x2 packed helpers (Blackwell FFMA2) ----
__device__ __forceinline__ ull pk2(float lo, float hi) {
    ull r; asm("mov.b64 %0,{%1,%2};" : "=l"(r) : "f"(lo), "f"(hi)); return r;
}
__device__ __forceinline__ ull dup2(float v) {
    ull r; asm("mov.b64 %0,{%1,%1};" : "=l"(r) : "f"(v)); return r;
}
__device__ __forceinline__ void fma2(ull& d, ull a, ull b) {
    asm("fma.rn.f32x2 %0,%1,%2,%0;" : "+l"(d) : "l"(a), "l"(b));
}
__device__ __forceinline__ float2 up2(ull v) {
    float2 r; asm("mov.b64 {%0,%1},%2;" : "=f"(r.x), "=f"(r.y) : "l"(v)); return r;
}

// Scratch: windowified Q/K/V  [b][head][n][pix4][dh]  (25MB each), 128B aligned
__device__ __align__(128) float g_Q[BB*NHEADS*P2*4*DH];
__device__ __align__(128) float g_K[BB*NHEADS*P2*4*DH];
__device__ __align__(128) float g_V[BB*NHEADS*P2*4*DH];

// ---------------------------------------------------------------------------
// Fused BN-fold + depthwise 5x5 conv for q,k,v (q pre-scaled by d^-0.5).
// Block: 128 thr = 32 channels x 4 col-slots, covering 4 rows x 32 cols.
// Grid: (24 chunks * 8 rowpairs, 8 b) = 1536 blocks (2x R6 for latency hiding).
// Folded weights pre-duplicated (f32x2) in SMEM; inner loop = LDS.64 + FFMA2.
// ---------------------------------------------------------------------------
__global__ __launch_bounds__(128) void conv_kernel(const float* __restrict__ x,
                                                   const float* __restrict__ conv_w,
                                                   const float* __restrict__ gamma,
                                                   const float* __restrict__ beta,
                                                   const float* __restrict__ mean,
                                                   const float* __restrict__ var) {
    __shared__ ull  wdup[3][25][32];
    __shared__ ull  bdup[3][32];
    __shared__ float sinv[3][32];

    int tid   = threadIdx.x;
    int b     = blockIdx.y;
    int chunk = blockIdx.x >> 3;
    int rpair = blockIdx.x & 7;       // 4-row band
    int lane5 = tid & 31;
    int slot  = tid >> 5;             // 0..3 -> col group
    int c0    = chunk * 32;
    int c     = c0 + lane5;

    if (tid < 96) {
        int j  = tid / 32;
        int cl = tid % 32;
        int t  = j * DD + c0 + cl;
        float inv = gamma[t] * rsqrtf(var[t] + 1e-5f);
        float bs  = beta[t] - mean[t] * inv;
        if (j == 0) { inv *= 0.03608439182435161f; bs *= 0.03608439182435161f; } // 768^-0.5
        sinv[j][cl] = inv;
        bdup[j][cl] = dup2(bs);
    }
    __syncthreads();
    for (int f = tid; f < 3 * 800; f += 128) {
        int j   = f / 800;
        int rem = f - j * 800;
        int ch  = rem / 25;
        int tap = rem - ch * 25;
        float wv = conv_w[(size_t)(j * DD + c0 + ch) * 25 + tap] * sinv[j][ch];
        wdup[j][tap][ch] = dup2(wv);
    }
    __syncthreads();

    ull biasr[3];
#pragma unroll
    for (int j = 0; j < 3; j++) biasr[j] = bdup[j][lane5];

    const float* xb = x + (size_t)b * 1024 * DD + c;
    int col0 = slot * 8;

#pragma unroll 1
    for (int gi = 0; gi < 4; gi++) {
        int row = rpair * 4 + gi;

        ull acc[3][4];
#pragma unroll
        for (int j = 0; j < 3; j++)
#pragma unroll
            for (int p = 0; p < 4; p++) acc[j][p] = biasr[j];

#pragma unroll
        for (int dy = 0; dy < 5; dy++) {
            int r = row + dy - 2;
            if ((unsigned)r < 32u) {
                const float* xr = xb + (size_t)(r * 32) * DD;
                float xv[12];
#pragma unroll
                for (int i = 0; i < 12; i++) {
                    int cl = col0 + i - 2;
                    xv[i] = ((unsigned)cl < 32u) ? xr[cl * DD] : 0.f;
                }
                ull xp[11];
#pragma unroll
                for (int i = 0; i < 11; i++) xp[i] = pk2(xv[i], xv[i + 1]);
#pragma unroll
                for (int j = 0; j < 3; j++) {
#pragma unroll
                    for (int dx = 0; dx < 5; dx++) {
                        ull wd = wdup[j][dy * 5 + dx][lane5];   // LDS.64 broadcast
                        fma2(acc[j][0], wd, xp[dx + 0]);
                        fma2(acc[j][1], wd, xp[dx + 2]);
                        fma2(acc[j][2], wd, xp[dx + 4]);
                        fma2(acc[j][3], wd, xp[dx + 6]);
                    }
                }
            }
        }

        int head  = c / DH;
        int cc    = c % DH;
        int pix   = ((row >> 4) << 1) + (col0 >> 4);
        int nbase = (row & 15) * 16 + (col0 & 15);
        int obase = (((b * NHEADS + head) * P2 + nbase) * 4 + pix) * DH + cc;
#pragma unroll
        for (int p = 0; p < 4; p++) {
            float2 aq = up2(acc[0][p]);
            float2 ak = up2(acc[1][p]);
            float2 av = up2(acc[2][p]);
            int off0 = obase + (2 * p) * (4 * DH);
            int off1 = off0 + 4 * DH;
            g_Q[off0] = aq.x;  g_Q[off1] = aq.y;
            g_K[off0] = ak.x;  g_K[off1] = ak.y;
            g_V[off0] = av.x;  g_V[off1] = av.y;
        }
    }
}

// ---------------------------------------------------------------------------
// Fused top-8 + sparse window attention. One warp per (b, head, window n).
// Flat-map coalesced gather (4 lines/LDG.128). K staged in smem, logits read
// it directly (no register reload). V prefetched to regs during logits, then
// overwrites the K buffer. Incremental REDUX top-8.
// ---------------------------------------------------------------------------
struct WarpSmem {
    float buf[32 * 52];   // K stage, then V  (float4-aligned rows)
    float qs[4 * 48];     // q (pre-scaled by conv)
    float at[128];        // softmax weights [kk][qp]
};

__global__ __launch_bounds__(128) void attn_kernel(const float* __restrict__ adj,
                                                   float* __restrict__ out) {
    __shared__ __align__(16) WarpSmem sm[4];
    const unsigned FULL = 0xffffffffu;
    int warp = threadIdx.x >> 5;
    int lane = threadIdx.x & 31;
    int widx = blockIdx.x * 4 + warp;      // 0..32767
    int bh   = widx >> 8;
    int n    = widx & 255;
    int b    = bh >> 4;
    int head = bh & 15;
    WarpSmem& S = sm[warp];

    // ---- stage q into smem early ----
    {
        const float4* qsrc = (const float4*)(g_Q + (size_t)widx * 192);
        ((float4*)S.qs)[lane] = qsrc[lane];
        if (lane < 16) ((float4*)S.qs)[32 + lane] = qsrc[32 + lane];
    }

    // ---- top-8: incremental monotone-uint REDUX argmax ----
    const float* rowp = adj + ((size_t)bh * 256 + n) * 256;
    unsigned m8[8];
#pragma unroll
    for (int j = 0; j < 8; j++) {
        unsigned u = __float_as_uint(rowp[j * 32 + lane]);
        m8[j] = (u & 0x80000000u) ? ~u : (u | 0x80000000u);
    }

    unsigned bv = m8[0];
    int bj = 0;
#pragma unroll
    for (int j = 1; j < 8; j++)
        if (m8[j] > bv) { bv = m8[j]; bj = j; }

    int mysel = 0;
#pragma unroll 1
    for (int it = 0; it < 8; it++) {
        unsigned wmax = __reduce_max_sync(FULL, bv);
        unsigned bal  = __ballot_sync(FULL, bv == wmax);
        int wl  = __ffs(bal) - 1;
        int bjw = __shfl_sync(FULL, bj, wl);
        if (lane == it) mysel = bjw * 32 + wl;
        if (lane == wl) {                      // only the losing lane rescans
            m8[bj] = 0u;
            bv = m8[0]; bj = 0;
#pragma unroll
            for (int j = 1; j < 8; j++)
                if (m8[j] > bv) { bv = m8[j]; bj = j; }
        }
    }

    // ---- flat-map gather precompute: inst j covers f4 indices j*32+lane ----
    int pack[12];
#pragma unroll
    for (int j = 0; j < 12; j++) {
        int f   = j * 32 + lane;
        int run = f / 48;
        int idx = f - run * 48;
        int pix = idx / 12;
        int c4  = idx - pix * 12;
        int sel = __shfl_sync(FULL, mysel, run);
        int goff = sel * 48 + idx;                 // f4 offset within bh region
        int slt  = (run * 4 + pix) * 13 + c4;      // smem f4 slot
        pack[j] = (goff << 9) | slt;
    }

    const float4* kg = (const float4*)g_K + (size_t)bh * 12288;
    const float4* vg = (const float4*)g_V + (size_t)bh * 12288;
    float4* buf4 = (float4*)S.buf;

    // ---- K gather -> smem (each inst: 512B contiguous, 4 lines) ----
#pragma unroll
    for (int j = 0; j < 12; j++)
        buf4[pack[j] & 511] = kg[pack[j] >> 9];
    __syncwarp();

    // ---- V prefetch into regs (latency hidden under logits) ----
    float4 V4[12];
#pragma unroll
    for (int j = 0; j < 12; j++) V4[j] = vg[pack[j] >> 9];

    // ---- logits: read own K column from buf directly (no reg staging) ----
    float l[4] = {0.f, 0.f, 0.f, 0.f};
    const float4* qs4 = (const float4*)S.qs;
#pragma unroll
    for (int ch = 0; ch < 12; ch++) {
        float4 kv = buf4[lane * 13 + ch];          // conflict-free (5*lane mod 8)
#pragma unroll
        for (int qp = 0; qp < 4; qp++) {
            float4 qv = qs4[qp * 12 + ch];         // broadcast LDS.128
            l[qp] += qv.x * kv.x + qv.y * kv.y + qv.z * kv.z + qv.w * kv.w;
        }
    }
    __syncwarp();                                  // all K reads done

    // ---- V -> smem (overwrites K buffer) ----
#pragma unroll
    for (int j = 0; j < 12; j++)
        buf4[pack[j] & 511] = V4[j];

    // ---- softmax across 32 lanes per qp-row ----
    float a[4];
#pragma unroll
    for (int qp = 0; qp < 4; qp++) {
        float m = l[qp];
#pragma unroll
        for (int off = 16; off > 0; off >>= 1)
            m = fmaxf(m, __shfl_xor_sync(FULL, m, off));
        float e = __expf(l[qp] - m);
        float s = e;
#pragma unroll
        for (int off = 16; off > 0; off >>= 1)
            s += __shfl_xor_sync(FULL, s, off);
        a[qp] = __fdividef(e, s);
    }
    ((float4*)S.at)[lane] = make_float4(a[0], a[1], a[2], a[3]);
    __syncwarp();

    // ---- out[qp][c] = sum_kk a[qp][kk] * v[kk][c] ----
    float o1[4] = {0,0,0,0}, o2[4] = {0,0,0,0};
#pragma unroll
    for (int kk = 0; kk < 32; kk++) {
        float4 av = ((const float4*)S.at)[kk];          // broadcast
        float v1 = S.buf[kk * 52 + lane];
        float v2 = S.buf[kk * 52 + 32 + lane];          // garbage for lane>=16, never stored
        o1[0] += av.x * v1; o1[1] += av.y * v1; o1[2] += av.z * v1; o1[3] += av.w * v1;
        o2[0] += av.x * v2; o2[1] += av.y * v2; o2[2] += av.z * v2; o2[3] += av.w * v2;
    }

    // ---- scatter to output ----
    int wy = n >> 4, wx = n & 15;
    float* ob = out + (size_t)b * 1024 * 768 + head * 48;
#pragma unroll
    for (int p = 0; p < 4; p++) {
        int row = ((p & 1) << 4) + wy;
        int col = ((p >> 1) << 4) + wx;
        int off = (row * 32 + col) * 768;
        ob[off + lane] = o1[p];
        if (lane < 16) ob[off + 32 + lane] = o2[p];
    }
}

// ---------------------------------------------------------------------------
extern "C" void kernel_launch(void* const* d_in, const int* in_sizes, int n_in,
                              void* d_out, int out_size) {
    const float* x      = (const float*)d_in[0];
    // d_in[1] = noise (unused by reference)
    const float* adj    = (const float*)d_in[2];
    const float* conv_w = (const float*)d_in[3];
    const float* gamma  = (const float*)d_in[4];
    const float* beta   = (const float*)d_in[5];
    const float* mean   = (const float*)d_in[6];
    const float* var    = (const float*)d_in[7];
    // d_in[8] = sparsity (constant 8, compiled in)
    float* out = (float*)d_out;

    conv_kernel<<<dim3(192, 8), 128>>>(x, conv_w, gamma, beta, mean, var);
    attn_kernel<<<8192, 128>>>(adj, out);
}